// round 16
// baseline (speedup 1.0000x reference)
#include <cuda_runtime.h>
#include <math.h>

#define LL 2
#define B 8
#define S 2048
#define D 2048
#define NH 16
#define HD 128
#define DC 4096
#define II 16384
#define PADTOK 50257

typedef unsigned long long u64;

__device__ __forceinline__ void ffma2(u64& d, u64 a, u64 b) {
    asm("fma.rn.f32x2 %0, %1, %2, %0;" : "+l"(d) : "l"(a), "l"(b));
}
__device__ __forceinline__ void fadd2(u64& d, u64 a) {
    asm("add.rn.f32x2 %0, %0, %1;" : "+l"(d) : "l"(a));
}
__device__ __forceinline__ u64 dup2(float a) {
    u64 r; asm("mov.b64 %0, {%1, %1};" : "=l"(r) : "f"(a)); return r;
}
__device__ __forceinline__ float f2sum(u64 a) {
    float2 v; memcpy(&v, &a, 8); return v.x + v.y;
}
__device__ __forceinline__ float f2lo(u64 a) { float2 v; memcpy(&v, &a, 8); return v.x; }
__device__ __forceinline__ float f2hi(u64 a) { float2 v; memcpy(&v, &a, 8); return v.y; }

// ---------------- scratch ----------------
__device__ int   g_idx[B];
__device__ float g_mean[LL][B][S];
__device__ float g_rstd[LL][B][S];
__device__ float g_qh[LL][B][D];
__device__ float g_qp[8][LL][B][D];      // q partials (csplit)
__device__ float g_Kg[LL][B][NH][D];     // g[d] * Kq[d]
__device__ float g_skp[8][LL][B][NH];    // partial sum g*Kq
__device__ float g_cbp[8][LL][B][NH];    // partial sum beta*Kq
__device__ float g_sc[LL][B][NH][S];     // scores, then A = w*rstd in place
__device__ float g_c0[LL][B][NH];
__device__ float g_ctx[LL][B][NH][D];
__device__ float g_ofp[8][LL][B][D];     // o_flat partials (dp split)
__device__ float g_wop[8][LL][B][D];     // wo partials (e split)
__device__ float g_attn[B][DC];
__device__ float g_p1[16][B][II];        // mlp1 partials
__device__ float g_m1[B][II];
__device__ float g_p2[64][B][DC];        // mlp2 partials
__device__ float g_h2[B][DC];

// ---------------- small kernels ----------------

__global__ void k_idx(const int* __restrict__ ids) {
    int b = blockIdx.x, t = threadIdx.x;
    __shared__ int red[256];
    int best = -1;
    for (int s = t; s < S; s += 256)
        if (ids[b * S + s] != PADTOK) best = (s > best) ? s : best;
    red[t] = best; __syncthreads();
    for (int o = 128; o; o >>= 1) { if (t < o) red[t] = max(red[t], red[t + o]); __syncthreads(); }
    if (t == 0) g_idx[b] = (red[0] < 0) ? 0 : red[0];
}

__global__ __launch_bounds__(256) void k_qh(const float* __restrict__ hs0, const float* __restrict__ hs1,
                                            const float* __restrict__ ln_g, const float* __restrict__ ln_b) {
    int b = blockIdx.x, l = blockIdx.y, t = threadIdx.x;
    const float* hs = l ? hs1 : hs0;
    int ix = g_idx[b];
    const float* row = hs + ((size_t)b * S + ix) * D;
    __shared__ float red[256];
    float s = 0.f, s2 = 0.f;
    for (int d = t; d < D; d += 256) { float v = row[d]; s += v; s2 += v * v; }
    red[t] = s; __syncthreads();
    for (int o = 128; o; o >>= 1) { if (t < o) red[t] += red[t + o]; __syncthreads(); }
    float tot = red[0]; __syncthreads();
    red[t] = s2; __syncthreads();
    for (int o = 128; o; o >>= 1) { if (t < o) red[t] += red[t + o]; __syncthreads(); }
    float tot2 = red[0]; __syncthreads();
    float mean = tot * (1.f / D);
    float var  = tot2 * (1.f / D) - mean * mean;
    float rstd = rsqrtf(var + 1e-5f);
    for (int d = t; d < D; d += 256)
        g_qh[l][b][d] = (row[d] - mean) * rstd * ln_g[l * D + d] + ln_b[l * D + d];
}

// ---------------- q projection: float4 weight stream, stripe reduce ----------------
__global__ __launch_bounds__(256) void k_qp(const float* __restrict__ Wq) {
    int ct = blockIdx.x, cs = blockIdx.y, l = blockIdx.z, t = threadIdx.x;
    int tr = t >> 6, la = t & 63;              // 4 row-stripes x 64 f4-cols
    __shared__ float qsh[8 * 256];
    __shared__ __align__(16) float4 rbuf[2048];   // [tr][bb][la]
    int c0 = cs * 256;
    for (int e = t; e < 2048; e += 256) { int bb = e >> 8, cc = e & 255; qsh[e] = g_qh[l][bb][c0 + cc]; }
    __syncthreads();
    float4 acc[8];
#pragma unroll
    for (int bb = 0; bb < 8; bb++) acc[bb] = make_float4(0.f, 0.f, 0.f, 0.f);
    const float* Wb = Wq + (size_t)l * D * D + (size_t)c0 * D + ct * 256 + la * 4;
#pragma unroll 8
    for (int i = 0; i < 64; i++) {
        int cc = i * 4 + tr;
        float4 wv = *(const float4*)(Wb + (size_t)cc * D);
#pragma unroll
        for (int bb = 0; bb < 8; bb++) {
            float a = qsh[bb * 256 + cc];
            acc[bb].x += a * wv.x; acc[bb].y += a * wv.y; acc[bb].z += a * wv.z; acc[bb].w += a * wv.w;
        }
    }
#pragma unroll
    for (int bb = 0; bb < 8; bb++) rbuf[(tr * 8 + bb) * 64 + la] = acc[bb];
    __syncthreads();
#pragma unroll
    for (int k = 0; k < 2; k++) {
        int o = t + k * 256;
        int bb = o >> 6, la2 = o & 63;
        float4 v  = rbuf[(0 * 8 + bb) * 64 + la2];
        float4 v1 = rbuf[(1 * 8 + bb) * 64 + la2];
        float4 v2 = rbuf[(2 * 8 + bb) * 64 + la2];
        float4 v3 = rbuf[(3 * 8 + bb) * 64 + la2];
        v.x += v1.x + v2.x + v3.x;
        v.y += v1.y + v2.y + v3.y;
        v.z += v1.z + v2.z + v3.z;
        v.w += v1.w + v2.w + v3.w;
        *(float4*)&g_qp[cs][l][bb][ct * 256 + la2 * 4] = v;
    }
}

// ---------------- Kq: smem-staged tiles, 8-lane reduce ----------------
#define WTS 132   // padded row stride (floats): 4-way floor, no worse
__global__ __launch_bounds__(256) void k_kqp(const float* __restrict__ Wk,
                                             const float* __restrict__ ln_g, const float* __restrict__ ln_b) {
    int h = blockIdx.x, p = blockIdx.y, l = blockIdx.z, t = threadIdx.x;
    __shared__ __align__(16) float qs[8 * 128];
    __shared__ __align__(16) float Wt[32 * WTS];
    __shared__ float sred[32][16];
    for (int e = t; e < 1024; e += 256) {
        int bb = e >> 7, j = e & 127;
        float s = 0.f;
#pragma unroll
        for (int pp = 0; pp < 8; pp++) s += g_qp[pp][l][bb][h * 128 + j];
        qs[e] = s;
    }
    __syncthreads();
    int rowl = t >> 3, part = t & 7;
    int c0 = part * 16;
    float skpA[8] = {0,0,0,0,0,0,0,0}, cbpA[8] = {0,0,0,0,0,0,0,0};
    const float* WbG = Wk + (size_t)l * D * D + (size_t)(p * 256) * D + h * 128;
    int ldrow = t >> 5, ldcol = t & 31;   // warp-per-row cooperative loads
    for (int tile = 0; tile < 8; tile++) {
        // stage 32x128 tile, coalesced, 4 float4 in flight per thread
#pragma unroll
        for (int j = 0; j < 4; j++) {
            int row = ldrow + j * 8;
            *(float4*)&Wt[row * WTS + ldcol * 4] =
                *(const float4*)(WbG + (size_t)(tile * 32 + row) * D + ldcol * 4);
        }
        __syncthreads();
        float4 w0 = *(const float4*)&Wt[rowl * WTS + c0];
        float4 w1 = *(const float4*)&Wt[rowl * WTS + c0 + 4];
        float4 w2 = *(const float4*)&Wt[rowl * WTS + c0 + 8];
        float4 w3 = *(const float4*)&Wt[rowl * WTS + c0 + 12];
        int dp = p * 256 + tile * 32 + rowl;
        float gd = ln_g[l * D + dp], bd = ln_b[l * D + dp];
        float kq[8];
#pragma unroll
        for (int bb = 0; bb < 8; bb++) {
            float4 q0 = *(const float4*)&qs[bb * 128 + c0];
            float4 q1 = *(const float4*)&qs[bb * 128 + c0 + 4];
            float4 q2 = *(const float4*)&qs[bb * 128 + c0 + 8];
            float4 q3 = *(const float4*)&qs[bb * 128 + c0 + 12];
            kq[bb] = w0.x*q0.x + w0.y*q0.y + w0.z*q0.z + w0.w*q0.w
                   + w1.x*q1.x + w1.y*q1.y + w1.z*q1.z + w1.w*q1.w
                   + w2.x*q2.x + w2.y*q2.y + w2.z*q2.z + w2.w*q2.w
                   + w3.x*q3.x + w3.y*q3.y + w3.z*q3.z + w3.w*q3.w;
        }
#pragma unroll
        for (int off = 4; off; off >>= 1)
#pragma unroll
            for (int bb = 0; bb < 8; bb++)
                kq[bb] += __shfl_xor_sync(0xffffffffu, kq[bb], off);
        if (part == 0) {
#pragma unroll
            for (int bb = 0; bb < 8; bb++) {
                float kg = gd * kq[bb];
                g_Kg[l][bb][h][dp] = kg;
                skpA[bb] += kg;
                cbpA[bb] += bd * kq[bb];
            }
        }
        __syncthreads();
    }
    if (part == 0) {
#pragma unroll
        for (int bb = 0; bb < 8; bb++) { sred[rowl][bb] = skpA[bb]; sred[rowl][8 + bb] = cbpA[bb]; }
    }
    __syncthreads();
    if (t < 16) {
        float s = 0.f;
        for (int r = 0; r < 32; r++) s += sred[r][t];
        if (t < 8) g_skp[p][l][t][h] = s;
        else       g_cbp[p][l][t - 8][h] = s;
    }
}

// ---------------- scores pass: fused LN stats, pipelined, f32x2 FMA ----------------
__global__ __launch_bounds__(256, 1) void k_scores(const float* __restrict__ hs0, const float* __restrict__ hs1) {
    int l = blockIdx.z, b = blockIdx.y;
    int s0 = blockIdx.x * 256;
    const float* hs = l ? hs1 : hs0;
    const int t = threadIdx.x;
    __shared__ __align__(16) float xs[256 * 36];
    __shared__ __align__(16) float kgs[16 * 36];
    __shared__ float smean[256], srstd[256];
    __shared__ float sskg[16], scb[16];
    if (t < 16) {
        float sk = 0.f, cc = 0.f;
#pragma unroll
        for (int p = 0; p < 8; p++) { sk += g_skp[p][l][b][t]; cc += g_cbp[p][l][b][t]; }
        sskg[t] = sk; scb[t] = cc;
    }
    const float* rowp = hs + ((size_t)b * S + s0 + t) * D;
    int kh = (t * 2) >> 5, kd = (t * 2) & 31;
    u64 rsp = 0ull, rs2p = 0ull;
    u64 acc2[4][4];
#pragma unroll
    for (int j = 0; j < 4; j++)
#pragma unroll
        for (int k = 0; k < 4; k++) acc2[j][k] = 0ull;
    int sg = t >> 2, hg = t & 3;
    ulonglong2 r2[8];
    {
        const ulonglong2* src = (const ulonglong2*)rowp;
#pragma unroll
        for (int q = 0; q < 8; q++) r2[q] = src[q];
    }
    float kA = g_Kg[l][b][kh][kd];
    float kB = g_Kg[l][b][kh][kd + 1];
    for (int d0 = 0; d0 < D; d0 += 32) {
        // commit prefetched chunk + packed LN stats
#pragma unroll
        for (int q = 0; q < 8; q++) {
            ulonglong2 v = r2[q];
            fadd2(rsp, v.x); fadd2(rsp, v.y);
            ffma2(rs2p, v.x, v.x); ffma2(rs2p, v.y, v.y);
            *(ulonglong2*)&xs[t * 36 + q * 4] = v;
        }
        kgs[kh * 36 + kd] = kA;
        kgs[kh * 36 + kd + 1] = kB;
        __syncthreads();
        if (d0 + 32 < D) {
            const ulonglong2* src = (const ulonglong2*)(rowp + d0 + 32);
#pragma unroll
            for (int q = 0; q < 8; q++) r2[q] = src[q];
            kA = g_Kg[l][b][kh][d0 + 32 + kd];
            kB = g_Kg[l][b][kh][d0 + 32 + kd + 1];
        }
#pragma unroll
        for (int dd = 0; dd < 32; dd += 4) {
            ulonglong2 x0 = *(const ulonglong2*)&xs[sg * 36 + dd];
            ulonglong2 x1 = *(const ulonglong2*)&xs[(sg + 64) * 36 + dd];
            ulonglong2 x2 = *(const ulonglong2*)&xs[(sg + 128) * 36 + dd];
            ulonglong2 x3 = *(const ulonglong2*)&xs[(sg + 192) * 36 + dd];
            ulonglong2 k0 = *(const ulonglong2*)&kgs[hg * 36 + dd];
            ulonglong2 k1 = *(const ulonglong2*)&kgs[(hg + 4) * 36 + dd];
            ulonglong2 k2 = *(const ulonglong2*)&kgs[(hg + 8) * 36 + dd];
            ulonglong2 k3 = *(const ulonglong2*)&kgs[(hg + 12) * 36 + dd];
#define DOT2(A, X, K) ffma2(A, X.x, K.x); ffma2(A, X.y, K.y);
            DOT2(acc2[0][0], x0, k0) DOT2(acc2[0][1], x0, k1) DOT2(acc2[0][2], x0, k2) DOT2(acc2[0][3], x0, k3)
            DOT2(acc2[1][0], x1, k0) DOT2(acc2[1][1], x1, k1) DOT2(acc2[1][2], x1, k2) DOT2(acc2[1][3], x1, k3)
            DOT2(acc2[2][0], x2, k0) DOT2(acc2[2][1], x2, k1) DOT2(acc2[2][2], x2, k2) DOT2(acc2[2][3], x2, k3)
            DOT2(acc2[3][0], x3, k0) DOT2(acc2[3][1], x3, k1) DOT2(acc2[3][2], x3, k2) DOT2(acc2[3][3], x3, k3)
#undef DOT2
        }
        __syncthreads();
    }
    float rs = f2sum(rsp), rs2 = f2sum(rs2p);
    float mean = rs * (1.f / D);
    float var  = rs2 * (1.f / D) - mean * mean;
    float rstd = rsqrtf(var + 1e-5f);
    g_mean[l][b][s0 + t] = mean;
    g_rstd[l][b][s0 + t] = rstd;
    smean[t] = mean; srstd[t] = rstd;
    __syncthreads();
#pragma unroll
    for (int j = 0; j < 4; j++) {
        int s = sg + j * 64;
        float m = smean[s], r2v = srstd[s];
#pragma unroll
        for (int k = 0; k < 4; k++) {
            int h = hg + k * 4;
            g_sc[l][b][h][s0 + s] = r2v * (f2sum(acc2[j][k]) - m * sskg[h]) + scb[h];
        }
    }
}

// ---------------- softmax; A = w*rstd in place; c0 ----------------
__global__ __launch_bounds__(256) void k_softmax() {
    int h = blockIdx.x, b = blockIdx.y, l = blockIdx.z, t = threadIdx.x;
    float* sc = &g_sc[l][b][h][0];
    __shared__ float buf[S];
    __shared__ float red[256];
    float mx = -1e30f;
    for (int s = t; s < S; s += 256) { float v = sc[s]; buf[s] = v; mx = fmaxf(mx, v); }
    red[t] = mx; __syncthreads();
    for (int o = 128; o; o >>= 1) { if (t < o) red[t] = fmaxf(red[t], red[t + o]); __syncthreads(); }
    mx = red[0]; __syncthreads();
    float sum = 0.f;
    for (int s = t; s < S; s += 256) { float e = expf(buf[s] - mx); buf[s] = e; sum += e; }
    red[t] = sum; __syncthreads();
    for (int o = 128; o; o >>= 1) { if (t < o) red[t] += red[t + o]; __syncthreads(); }
    float inv = 1.f / red[0]; __syncthreads();
    float c0 = 0.f;
    for (int s = t; s < S; s += 256) {
        float w = buf[s] * inv;
        float r = g_rstd[l][b][s], m = g_mean[l][b][s];
        sc[s] = w * r;
        c0 += w * r * m;
    }
    red[t] = c0; __syncthreads();
    for (int o = 128; o; o >>= 1) { if (t < o) red[t] += red[t + o]; __syncthreads(); }
    if (t == 0) g_c0[l][b][h] = red[0];
}

// ---------------- ctx pass, pipelined, f32x2 FMA (A duplicated pairs) ----------------
__global__ __launch_bounds__(256, 1) void k_ctx(const float* __restrict__ hs0, const float* __restrict__ hs1,
                                                const float* __restrict__ ln_g, const float* __restrict__ ln_b) {
    int l = blockIdx.z, b = blockIdx.y;
    int dt0 = blockIdx.x * 256;
    const float* hs = l ? hs1 : hs0;
    int t = threadIdx.x;
    __shared__ __align__(16) float xt[32 * 256];
    __shared__ __align__(16) u64 At2[16 * 36];
    __shared__ float sc0[16];
    if (t < 16) sc0[t] = g_c0[l][b][t];
    int dgrp = t & 63, hgrp = t >> 6;
    int ah = (t * 2) >> 5, as_ = (t * 2) & 31;
    ulonglong2 acc2[4];
#pragma unroll
    for (int k = 0; k < 4; k++) { acc2[k].x = 0ull; acc2[k].y = 0ull; }
    ulonglong2 r2[8];
#pragma unroll
    for (int w = 0; w < 8; w++) {
        int e4 = t + w * 256;
        int row = e4 >> 6, c4 = e4 & 63;
        r2[w] = *(const ulonglong2*)(hs + ((size_t)b * S + row) * D + dt0 + c4 * 4);
    }
    float aA = g_sc[l][b][ah][as_];
    float aB = g_sc[l][b][ah][as_ + 1];
    for (int s0 = 0; s0 < S; s0 += 32) {
#pragma unroll
        for (int w = 0; w < 8; w++) {
            int e4 = t + w * 256;
            int row = e4 >> 6, c4 = e4 & 63;
            *(ulonglong2*)&xt[row * 256 + c4 * 4] = r2[w];
        }
        At2[ah * 36 + as_] = dup2(aA);
        At2[ah * 36 + as_ + 1] = dup2(aB);
        __syncthreads();
        if (s0 + 32 < S) {
#pragma unroll
            for (int w = 0; w < 8; w++) {
                int e4 = t + w * 256;
                int row = e4 >> 6, c4 = e4 & 63;
                r2[w] = *(const ulonglong2*)(hs + ((size_t)b * S + s0 + 32 + row) * D + dt0 + c4 * 4);
            }
            aA = g_sc[l][b][ah][s0 + 32 + as_];
            aB = g_sc[l][b][ah][s0 + 32 + as_ + 1];
        }
#pragma unroll
        for (int ss = 0; ss < 32; ss += 4) {
            ulonglong2 xA = *(const ulonglong2*)&xt[(ss + 0) * 256 + dgrp * 4];
            ulonglong2 xB = *(const ulonglong2*)&xt[(ss + 1) * 256 + dgrp * 4];
            ulonglong2 xC = *(const ulonglong2*)&xt[(ss + 2) * 256 + dgrp * 4];
            ulonglong2 xD = *(const ulonglong2*)&xt[(ss + 3) * 256 + dgrp * 4];
#pragma unroll
            for (int k = 0; k < 4; k++) {
                ulonglong2 aP = *(const ulonglong2*)&At2[(hgrp + 4 * k) * 36 + ss];
                ulonglong2 aQ = *(const ulonglong2*)&At2[(hgrp + 4 * k) * 36 + ss + 2];
                ffma2(acc2[k].x, xA.x, aP.x); ffma2(acc2[k].y, xA.y, aP.x);
                ffma2(acc2[k].x, xB.x, aP.y); ffma2(acc2[k].y, xB.y, aP.y);
                ffma2(acc2[k].x, xC.x, aQ.x); ffma2(acc2[k].y, xC.y, aQ.x);
                ffma2(acc2[k].x, xD.x, aQ.y); ffma2(acc2[k].y, xD.y, aQ.y);
            }
        }
        __syncthreads();
    }
    int d = dt0 + dgrp * 4;
    float4 gd = *(const float4*)&ln_g[l * D + d];
    float4 bd = *(const float4*)&ln_b[l * D + d];
#pragma unroll
    for (int k = 0; k < 4; k++) {
        int h = hgrp + 4 * k;
        float c0h = sc0[h];
        float4 o;
        o.x = gd.x * (f2lo(acc2[k].x) - c0h) + bd.x;
        o.y = gd.y * (f2hi(acc2[k].x) - c0h) + bd.y;
        o.z = gd.z * (f2lo(acc2[k].y) - c0h) + bd.z;
        o.w = gd.w * (f2hi(acc2[k].y) - c0h) + bd.w;
        *(float4*)&g_ctx[l][b][h][d] = o;
    }
}

// ---------------- V projection: warp-per-row float4, stripe reduce ----------------
__global__ __launch_bounds__(256) void k_ovp(const float* __restrict__ Wv) {
    int h = blockIdx.x, ds = blockIdx.y, l = blockIdx.z, t = threadIdx.x;
    int w = t >> 5, la = t & 31;
    int dp0 = ds * 256;
    __shared__ float cs_[8 * 256];
    __shared__ __align__(16) float4 part[2048];    // [w][bb][la]
    for (int e = t; e < 2048; e += 256) { int bb = e >> 8, dd = e & 255; cs_[e] = g_ctx[l][bb][h][dp0 + dd]; }
    __syncthreads();
    float4 acc[8];
#pragma unroll
    for (int bb = 0; bb < 8; bb++) acc[bb] = make_float4(0.f, 0.f, 0.f, 0.f);
    const float* Wb = Wv + (size_t)l * D * D + (size_t)dp0 * D + h * 128 + la * 4;
#pragma unroll 4
    for (int i = 0; i < 32; i++) {
        int dpl = i * 8 + w;
        float4 wv = *(const float4*)(Wb + (size_t)dpl * D);
#pragma unroll
        for (int bb = 0; bb < 8; bb++) {
            float a = cs_[bb * 256 + dpl];
            acc[bb].x += a * wv.x; acc[bb].y += a * wv.y; acc[bb].z += a * wv.z; acc[bb].w += a * wv.w;
        }
    }
#pragma unroll
    for (int bb = 0; bb < 8; bb++) part[(w * 8 + bb) * 32 + la] = acc[bb];
    __syncthreads();
    {
        int bb = t >> 5, la2 = t & 31;
        float4 v = part[(0 * 8 + bb) * 32 + la2];
#pragma unroll
        for (int ww = 1; ww < 8; ww++) {
            float4 u = part[(ww * 8 + bb) * 32 + la2];
            v.x += u.x; v.y += u.y; v.z += u.z; v.w += u.w;
        }
        *(float4*)&g_ofp[ds][l][bb][h * 128 + la2 * 4] = v;
    }
}

// ---------------- Wo projection: float4 stream, sums g_ofp inline ----------------
__global__ __launch_bounds__(256) void k_wop(const float* __restrict__ Wo) {
    int ct = blockIdx.x, es = blockIdx.y, l = blockIdx.z, t = threadIdx.x;
    int tr = t >> 6, la = t & 63;
    int e0 = es * 256;
    __shared__ __align__(16) float os[8 * 256];
    __shared__ __align__(16) float4 rbuf[2048];
    for (int e = t; e < 512; e += 256) {
        int bb = e >> 6, ee4 = e & 63;
        float4 s = make_float4(0.f, 0.f, 0.f, 0.f);
#pragma unroll
        for (int pp = 0; pp < 8; pp++) {
            float4 u = *(const float4*)&g_ofp[pp][l][bb][e0 + ee4 * 4];
            s.x += u.x; s.y += u.y; s.z += u.z; s.w += u.w;
        }
        *(float4*)&os[bb * 256 + ee4 * 4] = s;
    }
    __syncthreads();
    float4 acc[8];
#pragma unroll
    for (int bb = 0; bb < 8; bb++) acc[bb] = make_float4(0.f, 0.f, 0.f, 0.f);
    const float* Wb = Wo + (size_t)l * D * D + (size_t)e0 * D + ct * 256 + la * 4;
#pragma unroll 8
    for (int i = 0; i < 64; i++) {
        int ee = i * 4 + tr;
        float4 wv = *(const float4*)(Wb + (size_t)ee * D);
#pragma unroll
        for (int bb = 0; bb < 8; bb++) {
            float a = os[bb * 256 + ee];
            acc[bb].x += a * wv.x; acc[bb].y += a * wv.y; acc[bb].z += a * wv.z; acc[bb].w += a * wv.w;
        }
    }
#pragma unroll
    for (int bb = 0; bb < 8; bb++) rbuf[(tr * 8 + bb) * 64 + la] = acc[bb];
    __syncthreads();
#pragma unroll
    for (int k = 0; k < 2; k++) {
        int o = t + k * 256;
        int bb = o >> 6, la2 = o & 63;
        float4 v  = rbuf[(0 * 8 + bb) * 64 + la2];
        float4 v1 = rbuf[(1 * 8 + bb) * 64 + la2];
        float4 v2 = rbuf[(2 * 8 + bb) * 64 + la2];
        float4 v3 = rbuf[(3 * 8 + bb) * 64 + la2];
        v.x += v1.x + v2.x + v3.x;
        v.y += v1.y + v2.y + v3.y;
        v.z += v1.z + v2.z + v3.z;
        v.w += v1.w + v2.w + v3.w;
        *(float4*)&g_wop[es][l][bb][ct * 256 + la2 * 4] = v;
    }
}

__global__ void k_wored(const float* __restrict__ bo) {
    int idx = blockIdx.x * 256 + threadIdx.x;  // LL*B*D
    int l = idx >> 14, r = idx & 16383, b = r >> 11, col = r & 2047;
    float s = bo[l * D + col];
#pragma unroll
    for (int p = 0; p < 8; p++) s += g_wop[p][l][b][col];
    g_attn[b][l * D + col] = s;
}

// ---------------- MLP: dual-row load streams ----------------
__global__ __launch_bounds__(256) void k_mlp1(const float* __restrict__ W1) {
    int it = blockIdx.x;   // 0..15 -> 256 float4-cols each
    int cs = blockIdx.y;   // 0..15 -> 256 rows each
    int t = threadIdx.x;
    int col4 = it * 256 + t;
    int cbase = cs * 256;
    __shared__ float as[8 * 256];
    for (int e = t; e < 2048; e += 256) { int bb = e >> 8, cc = e & 255; as[e] = g_attn[bb][cbase + cc]; }
    __syncthreads();
    float4 acc[8];
#pragma unroll
    for (int bb = 0; bb < 8; bb++) acc[bb] = make_float4(0.f, 0.f, 0.f, 0.f);
#pragma unroll 4
    for (int cc = 0; cc < 128; cc++) {
        float4 wa = *(const float4*)(W1 + (size_t)(cbase + cc) * II + col4 * 4);
        float4 wb = *(const float4*)(W1 + (size_t)(cbase + 128 + cc) * II + col4 * 4);
#pragma unroll
        for (int bb = 0; bb < 8; bb++) {
            float av = as[bb * 256 + cc];
            float bv = as[bb * 256 + 128 + cc];
            acc[bb].x += av * wa.x + bv * wb.x;
            acc[bb].y += av * wa.y + bv * wb.y;
            acc[bb].z += av * wa.z + bv * wb.z;
            acc[bb].w += av * wa.w + bv * wb.w;
        }
    }
    for (int bb = 0; bb < 8; bb++) *(float4*)&g_p1[cs][bb][col4 * 4] = acc[bb];
}

__global__ void k_gelu(const float* __restrict__ b1) {
    int e = blockIdx.x * 256 + threadIdx.x;
    int bb = e / II, i = e % II;
    float x = b1[i];
#pragma unroll
    for (int p = 0; p < 16; p++) x += g_p1[p][bb][i];
    g_m1[bb][i] = 0.5f * x * (1.0f + erff(x * 0.70710678118654752f));
}

__global__ __launch_bounds__(256) void k_mlp2(const float* __restrict__ W2) {
    int ct = blockIdx.x;   // 0..3 -> 256 float4-cols each
    int isp = blockIdx.y;  // 0..63 -> 256 rows each
    int t = threadIdx.x;
    int col4 = ct * 256 + t;
    int ibase = isp * 256;
    __shared__ float ms[8 * 256];
    for (int e = t; e < 2048; e += 256) { int bb = e >> 8, ii = e & 255; ms[e] = g_m1[bb][ibase + ii]; }
    __syncthreads();
    float4 acc[8];
#pragma unroll
    for (int bb = 0; bb < 8; bb++) acc[bb] = make_float4(0.f, 0.f, 0.f, 0.f);
#pragma unroll 4
    for (int ii = 0; ii < 128; ii++) {
        float4 wa = *(const float4*)(W2 + (size_t)(ibase + ii) * DC + col4 * 4);
        float4 wb = *(const float4*)(W2 + (size_t)(ibase + 128 + ii) * DC + col4 * 4);
#pragma unroll
        for (int bb = 0; bb < 8; bb++) {
            float av = ms[bb * 256 + ii];
            float bv = ms[bb * 256 + 128 + ii];
            acc[bb].x += av * wa.x + bv * wb.x;
            acc[bb].y += av * wa.y + bv * wb.y;
            acc[bb].z += av * wa.z + bv * wb.z;
            acc[bb].w += av * wa.w + bv * wb.w;
        }
    }
    for (int bb = 0; bb < 8; bb++) *(float4*)&g_p2[isp][bb][col4 * 4] = acc[bb];
}

__global__ void k_h2(const float* __restrict__ b2) {
    int e = blockIdx.x * 256 + threadIdx.x;
    int bb = e / DC, c = e % DC;
    float s = g_attn[bb][c] + b2[c];
#pragma unroll
    for (int i = 0; i < 64; i++) s += g_p2[i][bb][c];
    g_h2[bb][c] = s;
}

__global__ __launch_bounds__(256) void k_logits(const float* __restrict__ Wl, const float* __restrict__ bl,
                                                float* __restrict__ out) {
    int b = blockIdx.x >> 1, j = blockIdx.x & 1, t = threadIdx.x;
    __shared__ float red[256];
    float s = 0.f;
    for (int c = t; c < DC; c += 256) s += g_h2[b][c] * Wl[c * 2 + j];
    red[t] = s; __syncthreads();
    for (int o = 128; o; o >>= 1) { if (t < o) red[t] += red[t + o]; __syncthreads(); }
    if (t == 0) out[b * 2 + j] = red[0] + bl[j];
}

// ---------------- launch ----------------
extern "C" void kernel_launch(void* const* d_in, const int* in_sizes, int n_in,
                              void* d_out, int out_size) {
    const float* hs0  = (const float*)d_in[0];
    const float* hs1  = (const float*)d_in[1];
    const int*   ids  = (const int*)  d_in[2];
    const float* ln_g = (const float*)d_in[3];
    const float* ln_b = (const float*)d_in[4];
    const float* Wq   = (const float*)d_in[5];
    const float* Wk   = (const float*)d_in[6];
    const float* Wv   = (const float*)d_in[7];
    const float* Wo   = (const float*)d_in[8];
    const float* bo   = (const float*)d_in[9];
    const float* W1   = (const float*)d_in[10];
    const float* b1   = (const float*)d_in[11];
    const float* W2   = (const float*)d_in[12];
    const float* b2   = (const float*)d_in[13];
    const float* Wl   = (const float*)d_in[14];
    const float* bl   = (const float*)d_in[15];
    float* out = (float*)d_out;

    k_idx<<<B, 256>>>(ids);
    k_qh<<<dim3(B, LL), 256>>>(hs0, hs1, ln_g, ln_b);
    k_qp<<<dim3(8, 8, LL), 256>>>(Wq);
    k_kqp<<<dim3(NH, 8, LL), 256>>>(Wk, ln_g, ln_b);
    k_scores<<<dim3(S / 256, B, LL), 256>>>(hs0, hs1);
    k_softmax<<<dim3(NH, B, LL), 256>>>();
    k_ctx<<<dim3(D / 256, B, LL), 256>>>(hs0, hs1, ln_g, ln_b);
    k_ovp<<<dim3(NH, 8, LL), 256>>>(Wv);
    k_wop<<<dim3(8, 8, LL), 256>>>(Wo);
    k_wored<<<128, 256>>>(bo);
    k_mlp1<<<dim3(16, 16), 256>>>(W1);
    k_gelu<<<(B * II) / 256, 256>>>(b1);
    k_mlp2<<<dim3(4, 64), 256>>>(W2);
    k_h2<<<(B * DC) / 256, 256>>>(b2);
    k_logits<<<B * 2, 256>>>(Wl, bl, out);
}